// round 13
// baseline (speedup 1.0000x reference)
#include <cuda_runtime.h>
#include <cuda_bf16.h>
#include <cstdint>

#define BB 16
#define T_STEPS 20
#define NT 3009
#define GRID_CONV 592
#define SMEM_BYTES 20864

// ---------------- persistent device state ----------------
__device__ float g_v [BB*3*32*32];
__device__ float g_s [BB*3*32*32];
__device__ float g_m1[BB*64*32*32];     // NCHW
__device__ float g_o1[BB*64*32*32];     // NCHW
__device__ float g_m2[BB*16*16*128];    // NHWC
__device__ float g_o2[BB*16*16*128];    // NHWC
__device__ float g_m3[BB*16*16*128];    // NHWC
__device__ float g_o3[BB*16*16*128];    // NHWC
__device__ float g_f [BB*8192];
__device__ float g_m4[BB*1024];
__device__ float g_o4[BB*1024];
__device__ float g_m5[BB*1024];
__device__ float g_o5[BB*1024];
__device__ float g_mo[BB*10];
__device__ int   g_tick;

// conv1 slab + K-split slabs (deterministic summation in spike_step)
__device__ float g_c1s[BB*64*32*32];        // conv1 raw out, NCHW
__device__ float g_s2 [6][BB*16*16*128];    // conv2: 3 terms x 2 kc
__device__ float g_s3 [12][BB*16*16*128];   // conv3: 3 terms x 4 kc
__device__ float g_s4 [32][BB*1024];        // fc1: 32 k-splits
__device__ float g_s5 [4][BB*1024];         // fc2: 4 k-splits

// bf16 activations, channel-last, zero halo [b][18][18][C]
__device__ __nv_bfloat16 g_a2[BB*18*18*64];    // conv2 input (pooled conv1)
__device__ __nv_bfloat16 g_a3[BB*18*18*128];   // conv3 input (conv2 spikes)

// bf16 3-term split weights in mma-B-FRAGMENT order (verified R11/R12):
// [t3*9+dydx][kc][nq][lane][kk*16 + nb8*4 + r*2 + h]
__device__ __align__(16) __nv_bfloat16 g_w2t[3*9*64*128];
__device__ __align__(16) __nv_bfloat16 g_w3t[3*9*128*128];

// ---------------- zero state ----------------
__global__ void zero_state() {
    int n  = gridDim.x * blockDim.x;
    int i0 = blockIdx.x * blockDim.x + threadIdx.x;
    for (int i = i0; i < BB*3*32*32;   i += n) { g_v[i] = 0.f; g_s[i] = 0.f; }
    for (int i = i0; i < BB*64*32*32;  i += n) { g_m1[i] = 0.f; g_o1[i] = 0.f; g_c1s[i] = 0.f; }
    for (int i = i0; i < BB*16*16*128; i += n) {
        g_m2[i] = 0.f; g_o2[i] = 0.f; g_m3[i] = 0.f; g_o3[i] = 0.f;
        #pragma unroll
        for (int k = 0; k < 6;  k++) g_s2[k][i] = 0.f;
        #pragma unroll
        for (int k = 0; k < 12; k++) g_s3[k][i] = 0.f;
    }
    for (int i = i0; i < BB*18*18*64;  i += n) g_a2[i] = __float2bfloat16(0.f);
    for (int i = i0; i < BB*18*18*128; i += n) g_a3[i] = __float2bfloat16(0.f);
    for (int i = i0; i < BB*1024; i += n) {
        g_m4[i] = 0.f; g_o4[i] = 0.f; g_m5[i] = 0.f; g_o5[i] = 0.f;
        #pragma unroll
        for (int k = 0; k < 32; k++) g_s4[k][i] = 0.f;
        #pragma unroll
        for (int k = 0; k < 4;  k++) g_s5[k][i] = 0.f;
    }
    for (int i = i0; i < BB*10; i += n) g_mo[i] = 0.f;
}

// ---------------- weight preprocessing: 3-term split, B-fragment order ----------------
__global__ void prep_weights(const float* __restrict__ W2, const float* __restrict__ W3) {
    int i = blockIdx.x * blockDim.x + threadIdx.x;
    if (i < 442368) {                        // conv3
        int h = i & 1, r = (i >> 1) & 1, nb8 = (i >> 2) & 3, kk = (i >> 4) & 1;
        int lane = (i >> 5) & 31, nq = (i >> 10) & 3, kc = (i >> 12) & 3;
        int rest = i >> 14;                  // 0..26
        int dydx = rest % 9, t3 = rest / 9;
        int c  = kc*32 + kk*16 + (lane & 3)*2 + r*8 + h;
        int oc = nq*32 + nb8*8 + (lane >> 2);
        float w = W3[(oc*128 + c)*9 + dydx];
        __nv_bfloat16 hi = __float2bfloat16_rn(w);
        float r1 = w - __bfloat162float(hi);
        __nv_bfloat16 mi = __float2bfloat16_rn(r1);
        float r2 = r1 - __bfloat162float(mi);
        __nv_bfloat16 lo = __float2bfloat16_rn(r2);
        g_w3t[i] = (t3 == 0) ? hi : (t3 == 1) ? mi : lo;
    } else if (i < 663552) {                 // conv2
        int j = i - 442368;
        int h = j & 1, r = (j >> 1) & 1, nb8 = (j >> 2) & 3, kk = (j >> 4) & 1;
        int lane = (j >> 5) & 31, nq = (j >> 10) & 3, kc = (j >> 12) & 1;
        int rest = j >> 13;                  // 0..26
        int dydx = rest % 9, t3 = rest / 9;
        int c  = kc*32 + kk*16 + (lane & 3)*2 + r*8 + h;
        int oc = nq*32 + nb8*8 + (lane >> 2);
        float w = W2[(oc*64 + c)*9 + dydx];
        __nv_bfloat16 hi = __float2bfloat16_rn(w);
        float r1 = w - __bfloat162float(hi);
        __nv_bfloat16 mi = __float2bfloat16_rn(r1);
        float r2 = r1 - __bfloat162float(mi);
        __nv_bfloat16 lo = __float2bfloat16_rn(r2);
        g_w2t[j] = (t3 == 0) ? hi : (t3 == 1) ? mi : lo;
    }
}

// ---------------- per-step spike kernel ----------------
__global__ void __launch_bounds__(256) spike_step(const float* __restrict__ x) {
    int i = blockIdx.x * 256 + threadIdx.x;
    if (i == 0) g_tick = 0;
    if (i < 49152) {
        float v = g_v[i] + x[i];
        v = v - g_s[i];
        g_v[i] = v;
        g_s[i] = (v > 1.0f) ? 1.0f : 0.0f;
    } else if (i < 311296) {
        int p  = i - 49152;                  // (b,64c,16py,16px)
        int px = p & 15, py = (p >> 4) & 15, bc = p >> 8;
        int b = bc >> 6, c = bc & 63;
        int base = (bc*32 + py*2)*32 + px*2;
        float sum = 0.f;
        #pragma unroll
        for (int dy = 0; dy < 2; dy++)
            #pragma unroll
            for (int dx = 0; dx < 2; dx++) {
                int idx = base + dy*32 + dx;
                float m = (g_m1[idx] + g_c1s[idx]) - g_o1[idx];
                float o = (m > 1.0f) ? 1.0f : 0.0f;
                g_m1[idx] = m;
                g_o1[idx] = o;
                sum += o;
            }
        g_a2[((b*18 + py + 1)*18 + px + 1)*64 + c] = __float2bfloat16(sum * 0.25f);
    } else if (i < 835584) {
        int p = i - 311296;
        int c = p & 127, xx = (p >> 7) & 15, y = (p >> 11) & 15, b = p >> 15;
        float inp = 0.f;
        #pragma unroll
        for (int k = 0; k < 6; k++) inp += g_s2[k][p];
        float m = (g_m2[p] + inp) - g_o2[p];
        float o = (m > 1.0f) ? 1.0f : 0.0f;
        g_m2[p] = m;
        g_o2[p] = o;
        g_a3[((b*18 + y + 1)*18 + xx + 1)*128 + c] = __float2bfloat16(o);
    } else if (i < 966656) {
        int p = i - 835584;                  // (b, 8py, 8px, 128c)
        int c = p & 127, px = (p >> 7) & 7, py = (p >> 10) & 7, b = p >> 13;
        float sum = 0.f;
        #pragma unroll
        for (int dy = 0; dy < 2; dy++)
            #pragma unroll
            for (int dx = 0; dx < 2; dx++) {
                int idx = ((b*16 + 2*py + dy)*16 + 2*px + dx)*128 + c;
                float inp = 0.f;
                #pragma unroll
                for (int k = 0; k < 12; k++) inp += g_s3[k][idx];
                float m = (g_m3[idx] + inp) - g_o3[idx];
                float o = (m > 1.0f) ? 1.0f : 0.0f;
                g_m3[idx] = m;
                g_o3[idx] = o;
                sum += o;
            }
        g_f[b*8192 + c*64 + py*8 + px] = sum * 0.25f;
    } else if (i < 983040) {
        int p = i - 966656;
        float inp = 0.f;
        #pragma unroll 8
        for (int k = 0; k < 32; k++) inp += g_s4[k][p];
        float m = (g_m4[p] + inp) - g_o4[p];
        g_m4[p] = m;
        g_o4[p] = (m > 1.0f) ? 1.0f : 0.0f;
    } else if (i < 999424) {
        int p = i - 983040;
        float inp = ((g_s5[0][p] + g_s5[1][p]) + g_s5[2][p]) + g_s5[3][p];
        float m = (g_m5[p] + inp) - g_o5[p];
        g_m5[p] = m;
        g_o5[p] = (m > 1.0f) ? 1.0f : 0.0f;
    }
}

#define MMA_BF16(D, R0, R1, R2, R3, B0, B1) \
    asm volatile("mma.sync.aligned.m16n8k16.row.col.f32.bf16.bf16.f32 " \
                 "{%0,%1,%2,%3}, {%4,%5,%6,%7}, {%8,%9}, {%0,%1,%2,%3};\n" \
                 : "+f"((D)[0]), "+f"((D)[1]), "+f"((D)[2]), "+f"((D)[3]) \
                 : "r"(R0), "r"(R1), "r"(R2), "r"(R3), "r"(B0), "r"(B1))

// ---------------- tensor-core conv split-tile (9 stages, barrier-free) ----------------
// One tile = b x 2 y-rows x 128 oc x ONE (term, kc) split: 9 dydx stages at
// fixed kc, fully unrolled so ptxas pipelines the B loads across stages.
// 8 warps: wm = wid&1 (y-row, m16 = 16 px), nq = wid>>1 (32-oc quarter).
__device__ __forceinline__ void gemm_conv_tile(
    const __nv_bfloat16* __restrict__ act, const __nv_bfloat16* __restrict__ Wt,
    float* __restrict__ slab, int CIN, int n_kc, int t3, int kc,
    int b, int y0, float* smf)
{
    const int PS = CIN + 8;
    __nv_bfloat16* As = (__nv_bfloat16*)smf;
    unsigned as_u = (unsigned)__cvta_generic_to_shared(As);
    const int tid = threadIdx.x, wid = tid >> 5, lane = tid & 31;
    const int wm = wid & 1, nq = wid >> 1;
    const int mr = lane & 15, kh = lane >> 4;

    // ---- A slab fill: 4 halo rows x 18 px x CIN ----
    {
        const int cpp = CIN >> 3;
        const int CPR = 18 * cpp;
        const int TOT = 4 * CPR;
        for (int i = tid; i < TOT; i += 256) {
            int r = i / CPR; int rr = i - r*CPR;
            int px = rr / cpp; int inner = rr - px*cpp;
            uint4 v = *(const uint4*)(act + (((b*18 + y0 + r)*18 + px)*CIN) + inner*8);
            *(uint4*)(As + (r*18 + px)*PS + inner*8) = v;
        }
    }
    __syncthreads();

    float d[4][4];
    #pragma unroll
    for (int nb = 0; nb < 4; nb++)
        #pragma unroll
        for (int q = 0; q < 4; q++) d[nb][q] = 0.f;

    const int bstride = n_kc * 4096;
    const __nv_bfloat16* bp = Wt + (t3*9*n_kc + kc)*4096 + nq*1024 + lane*32;
    const unsigned koff = (unsigned)(kc * 64);

    #pragma unroll
    for (int dy = 0; dy < 3; dy++)
        #pragma unroll
        for (int dx = 0; dx < 3; dx++) {
            uint4 c0 = *(const uint4*)(bp);
            uint4 c1 = *(const uint4*)(bp + 8);
            uint4 c2 = *(const uint4*)(bp + 16);
            uint4 c3 = *(const uint4*)(bp + 24);
            unsigned ab = as_u + (unsigned)((((wm + dy)*18 + mr + dx)*PS + kh*8) * 2) + koff;
            unsigned r0, r1, r2, r3;
            // kk = 0
            asm volatile("ldmatrix.sync.aligned.m8n8.x4.shared.b16 {%0,%1,%2,%3}, [%4];\n"
                         : "=r"(r0), "=r"(r1), "=r"(r2), "=r"(r3) : "r"(ab));
            MMA_BF16(d[0], r0, r1, r2, r3, c0.x, c0.y);
            MMA_BF16(d[1], r0, r1, r2, r3, c0.z, c0.w);
            MMA_BF16(d[2], r0, r1, r2, r3, c1.x, c1.y);
            MMA_BF16(d[3], r0, r1, r2, r3, c1.z, c1.w);
            // kk = 1
            asm volatile("ldmatrix.sync.aligned.m8n8.x4.shared.b16 {%0,%1,%2,%3}, [%4];\n"
                         : "=r"(r0), "=r"(r1), "=r"(r2), "=r"(r3) : "r"(ab + 32));
            MMA_BF16(d[0], r0, r1, r2, r3, c2.x, c2.y);
            MMA_BF16(d[1], r0, r1, r2, r3, c2.z, c2.w);
            MMA_BF16(d[2], r0, r1, r2, r3, c3.x, c3.y);
            MMA_BF16(d[3], r0, r1, r2, r3, c3.z, c3.w);
            bp += bstride;
        }

    // ---- store: frag row = x pixel, cols = oc ----
    int xr = lane >> 2, nc0 = (lane & 3)*2;
    float* obase = slab + (((b*16 + y0 + wm)*16 + xr)*128 + nq*32 + nc0);
    #pragma unroll
    for (int nb = 0; nb < 4; nb++) {
        *(float2*)(obase + nb*8)        = make_float2(d[nb][0], d[nb][1]);
        *(float2*)(obase + nb*8 + 1024) = make_float2(d[nb][2], d[nb][3]);
    }
}

// ---------------- conv1 tile (3 in-ch, 32x32), 4 units of 256 ----------------
__device__ __forceinline__ void conv1_tile(
    const float* __restrict__ s, const float* __restrict__ W1,
    float* __restrict__ slab, int tile, float* sm)
{
    int tid = threadIdx.x;
    for (int idx = tid; idx < 1728; idx += 256) sm[idx] = W1[idx];
    __syncthreads();
    #pragma unroll 1
    for (int u4 = 0; u4 < 4; u4++) {
        int u   = (tile*4 + u4)*256 + tid;
        int row = u >> 2;
        int xb  = (u & 3) * 8;
        int b   = row >> 11;
        int oc  = (row >> 5) & 63;
        int y   = row & 31;
        float acc[8];
        #pragma unroll
        for (int i = 0; i < 8; i++) acc[i] = 0.f;
        #pragma unroll
        for (int c = 0; c < 3; c++) {
            #pragma unroll
            for (int dy = 0; dy < 3; dy++) {
                int gy = y + dy - 1;
                if ((unsigned)gy >= 32u) continue;
                const float* srow = s + ((b*3 + c)*32 + gy)*32;
                float iv[10];
                #pragma unroll
                for (int t = 0; t < 10; t++) {
                    int gx = xb + t - 1;
                    iv[t] = ((unsigned)gx < 32u) ? srow[gx] : 0.f;
                }
                float w[3];
                #pragma unroll
                for (int dx = 0; dx < 3; dx++) w[dx] = sm[oc*27 + c*9 + dy*3 + dx];
                #pragma unroll
                for (int i = 0; i < 8; i++)
                    #pragma unroll
                    for (int dx = 0; dx < 3; dx++)
                        acc[i] += iv[i + dx] * w[dx];
            }
        }
        int base = ((b*64 + oc)*32 + y)*32 + xb;
        #pragma unroll
        for (int i = 0; i < 8; i++) slab[base + i] = acc[i];
    }
}

// ---------------- FC tile: out[b,j] = A[b,k0:k0+256] . W[j,k0:k0+256] ----------------
__device__ __forceinline__ void fc_tile(
    const float* __restrict__ A, const float* __restrict__ W,
    float* __restrict__ out, int K, int j0, int k0, float* sm)
{
    float* fs = sm;          // [16][64]
    float* ws = sm + 1024;   // [64][65]
    int tid = threadIdx.x;
    int tj  = tid & 31;
    int tb  = tid >> 5;
    float acc[2][2] = {{0.f,0.f},{0.f,0.f}};
    #pragma unroll 1
    for (int kc = k0; kc < k0 + 256; kc += 64) {
        __syncthreads();
        for (int idx = tid; idx < 1024; idx += 256) {
            int bb = idx >> 6, kk = idx & 63;
            fs[idx] = A[bb*K + kc + kk];
        }
        for (int idx = tid; idx < 4096; idx += 256) {
            int jl = idx >> 6, kk = idx & 63;
            ws[jl*65 + kk] = W[(j0 + jl)*K + kc + kk];
        }
        __syncthreads();
        #pragma unroll 4
        for (int kk = 0; kk < 64; kk++) {
            float w0 = ws[(tj*2    )*65 + kk];
            float w1 = ws[(tj*2 + 1)*65 + kk];
            float f0 = fs[ tb      *64 + kk];
            float f1 = fs[(tb + 8) *64 + kk];
            acc[0][0] += w0*f0;  acc[0][1] += w0*f1;
            acc[1][0] += w1*f0;  acc[1][1] += w1*f1;
        }
    }
    #pragma unroll
    for (int q = 0; q < 2; q++)
        #pragma unroll
        for (int r = 0; r < 2; r++)
            out[(tb + r*8)*1024 + (j0 + tj*2 + q)] = acc[q][r];
}

// ---------------- fc3: mo += o5 @ L3^T ----------------
__device__ __forceinline__ void fc3_part(
    const float* __restrict__ o5, const float* __restrict__ L3, float* __restrict__ mo)
{
    int t = threadIdx.x;
    if (t >= 160) return;
    int b = t / 10, j = t - b*10;
    const float* a = o5 + b*1024;
    const float* w = L3 + j*1024;
    float acc = 0.f;
    #pragma unroll 4
    for (int k = 0; k < 1024; k++) acc += a[k]*w[k];
    mo[t] += acc;
}

// ---------------- fat per-step kernel: work queue over 3009 tiles ----------------
__global__ void __launch_bounds__(256, 4) conv_step(
    const float* __restrict__ W1, const float* __restrict__ L1,
    const float* __restrict__ L2, const float* __restrict__ L3)
{
    extern __shared__ float smf[];
    __shared__ int s_tile;
    for (;;) {
        __syncthreads();
        if (threadIdx.x == 0) s_tile = atomicAdd(&g_tick, 1);
        __syncthreads();
        int t = s_tile;
        if (t >= NT) return;
        if (t < 1536) {                      // conv3: 128 (b,y-pair) x 12 ksplits
            int ks = t % 12;                 // t3 = ks>>2, kc = ks&3
            int rest = t / 12;
            int b = rest >> 3, y0 = (rest & 7)*2;
            gemm_conv_tile(g_a3, g_w3t, &g_s3[ks][0], 128, 4, ks >> 2, ks & 3, b, y0, smf);
        } else if (t < 2304) {               // conv2: 128 x 6 ksplits
            int i = t - 1536;
            int ks = i % 6;                  // t3 = ks>>1, kc = ks&1
            int rest = i / 6;
            int b = rest >> 3, y0 = (rest & 7)*2;
            gemm_conv_tile(g_a2, g_w2t, &g_s2[ks][0], 64, 2, ks >> 1, ks & 1, b, y0, smf);
        } else if (t < 2816) {               // fc1: 16jg x 32ks
            int i = t - 2304;
            int jg = i & 15, ks = i >> 4;
            fc_tile(g_f, L1, &g_s4[ks][0], 8192, jg*64, ks*256, smf);
        } else if (t < 2944) {               // conv1: 128 tiles x 4 units
            conv1_tile(g_s, W1, g_c1s, t - 2816, smf);
        } else if (t < 3008) {               // fc2: 16jg x 4ks
            int i = t - 2944;
            int jg = i & 15, ks = i >> 4;
            fc_tile(g_o4, L2, &g_s5[ks][0], 1024, jg*64, ks*256, smf);
        } else {                             // fc3
            fc3_part(g_o5, L3, g_mo);
        }
    }
}

__global__ void write_out(float* __restrict__ out) {
    int t = threadIdx.x;
    if (t < 160) out[t] = g_mo[t];
}

extern "C" void kernel_launch(void* const* d_in, const int* in_sizes, int n_in,
                              void* d_out, int out_size)
{
    const float* x  = (const float*)d_in[0];
    const float* W1 = (const float*)d_in[1];
    const float* W2 = (const float*)d_in[2];
    const float* W3 = (const float*)d_in[3];
    const float* L1 = (const float*)d_in[4];
    const float* L2 = (const float*)d_in[5];
    const float* L3 = (const float*)d_in[6];

    cudaFuncSetAttribute(conv_step, cudaFuncAttributeMaxDynamicSharedMemorySize, SMEM_BYTES);

    zero_state<<<512, 256>>>();
    prep_weights<<<2592, 256>>>(W2, W3);
    for (int t = 0; t < T_STEPS; t++) {
        spike_step<<<3904, 256>>>(x);
        conv_step<<<GRID_CONV, 256, SMEM_BYTES>>>(W1, L1, L2, L3);
    }
    write_out<<<1, 192>>>((float*)d_out);
}

// round 14
// speedup vs baseline: 1.4709x; 1.4709x over previous
#include <cuda_runtime.h>
#include <cuda_bf16.h>
#include <cstdint>

#define BB 16
#define T_STEPS 20
#define NT 961
#define GRID_CONV 592
#define SMEM_BYTES 55296

// ---------------- persistent device state ----------------
__device__ float g_v [BB*3*32*32];
__device__ float g_s [BB*3*32*32];
__device__ float g_m1[BB*64*32*32];     // NCHW
__device__ float g_o1[BB*64*32*32];     // NCHW
__device__ float g_m2[BB*16*16*128];    // NHWC
__device__ float g_o2[BB*16*16*128];    // NHWC
__device__ float g_m3[BB*16*16*128];    // NHWC
__device__ float g_o3[BB*16*16*128];    // NHWC
__device__ float g_f [BB*8192];
__device__ float g_m4[BB*1024];
__device__ float g_o4[BB*1024];
__device__ float g_m5[BB*1024];
__device__ float g_o5[BB*1024];
__device__ float g_mo[BB*10];
__device__ int   g_tick;

// conv slabs (single, NHWC) + fc K-split slabs
__device__ float g_c1s[BB*64*32*32];    // conv1 raw out, NCHW
__device__ float g_s2 [BB*16*16*128];   // conv2 out, NHWC
__device__ float g_s3 [BB*16*16*128];   // conv3 out, NHWC
__device__ float g_s4 [32][BB*1024];    // fc1: 32 k-splits
__device__ float g_s5 [4][BB*1024];     // fc2: 4 k-splits

// bf16 activations, channel-last, zero halo [b][18][18][C]
__device__ __nv_bfloat16 g_a2[BB*18*18*64];    // conv2 input (pooled conv1)
__device__ __nv_bfloat16 g_a3[BB*18*18*128];   // conv3 input (conv2 spikes)

// bf16 3-term split weights, linear stream [term][dydx][c][oc]  (R9 layout)
__device__ __align__(16) __nv_bfloat16 g_w2t[3*9*64*128];
__device__ __align__(16) __nv_bfloat16 g_w3t[3*9*128*128];

// ---------------- zero state ----------------
__global__ void zero_state() {
    int n  = gridDim.x * blockDim.x;
    int i0 = blockIdx.x * blockDim.x + threadIdx.x;
    for (int i = i0; i < BB*3*32*32;   i += n) { g_v[i] = 0.f; g_s[i] = 0.f; }
    for (int i = i0; i < BB*64*32*32;  i += n) { g_m1[i] = 0.f; g_o1[i] = 0.f; g_c1s[i] = 0.f; }
    for (int i = i0; i < BB*16*16*128; i += n) {
        g_m2[i] = 0.f; g_o2[i] = 0.f; g_m3[i] = 0.f; g_o3[i] = 0.f;
        g_s2[i] = 0.f; g_s3[i] = 0.f;
    }
    for (int i = i0; i < BB*18*18*64;  i += n) g_a2[i] = __float2bfloat16(0.f);
    for (int i = i0; i < BB*18*18*128; i += n) g_a3[i] = __float2bfloat16(0.f);
    for (int i = i0; i < BB*1024; i += n) {
        g_m4[i] = 0.f; g_o4[i] = 0.f; g_m5[i] = 0.f; g_o5[i] = 0.f;
        #pragma unroll
        for (int k = 0; k < 32; k++) g_s4[k][i] = 0.f;
        #pragma unroll
        for (int k = 0; k < 4;  k++) g_s5[k][i] = 0.f;
    }
    for (int i = i0; i < BB*10; i += n) g_mo[i] = 0.f;
}

// ---------------- weight preprocessing: 3-term bf16 split (R9 layout) ----------------
__global__ void prep_weights(const float* __restrict__ W2, const float* __restrict__ W3) {
    int i = blockIdx.x * blockDim.x + threadIdx.x;
    float w; int dst;
    if (i < 147456) {                       // conv3: 9 dydx * 128 c * 128 oc
        int oc = i & 127, c = (i >> 7) & 127, dydx = i >> 14;
        w = W3[(oc*128 + c)*9 + dydx];
        dst = dydx*16384 + c*128 + oc;
        __nv_bfloat16 h = __float2bfloat16_rn(w);
        float r1 = w - __bfloat162float(h);
        __nv_bfloat16 m = __float2bfloat16_rn(r1);
        float r2 = r1 - __bfloat162float(m);
        __nv_bfloat16 l = __float2bfloat16_rn(r2);
        g_w3t[dst] = h; g_w3t[147456 + dst] = m; g_w3t[294912 + dst] = l;
    } else if (i < 221184) {                // conv2: 9 * 64 * 128
        int j = i - 147456;
        int oc = j & 127, c = (j >> 7) & 63, dydx = j >> 13;
        w = W2[(oc*64 + c)*9 + dydx];
        dst = dydx*8192 + c*128 + oc;
        __nv_bfloat16 h = __float2bfloat16_rn(w);
        float r1 = w - __bfloat162float(h);
        __nv_bfloat16 m = __float2bfloat16_rn(r1);
        float r2 = r1 - __bfloat162float(m);
        __nv_bfloat16 l = __float2bfloat16_rn(r2);
        g_w2t[dst] = h; g_w2t[73728 + dst] = m; g_w2t[147456 + dst] = l;
    }
}

// ---------------- per-step spike kernel ----------------
__global__ void __launch_bounds__(256) spike_step(const float* __restrict__ x) {
    int i = blockIdx.x * 256 + threadIdx.x;
    if (i == 0) g_tick = 0;
    if (i < 49152) {
        float v = g_v[i] + x[i];
        v = v - g_s[i];
        g_v[i] = v;
        g_s[i] = (v > 1.0f) ? 1.0f : 0.0f;
    } else if (i < 311296) {
        int p  = i - 49152;                  // (b,64c,16py,16px)
        int px = p & 15, py = (p >> 4) & 15, bc = p >> 8;
        int b = bc >> 6, c = bc & 63;
        int base = (bc*32 + py*2)*32 + px*2;
        float sum = 0.f;
        #pragma unroll
        for (int dy = 0; dy < 2; dy++)
            #pragma unroll
            for (int dx = 0; dx < 2; dx++) {
                int idx = base + dy*32 + dx;
                float m = (g_m1[idx] + g_c1s[idx]) - g_o1[idx];
                float o = (m > 1.0f) ? 1.0f : 0.0f;
                g_m1[idx] = m;
                g_o1[idx] = o;
                sum += o;
            }
        g_a2[((b*18 + py + 1)*18 + px + 1)*64 + c] = __float2bfloat16(sum * 0.25f);
    } else if (i < 835584) {
        int p = i - 311296;
        int c = p & 127, xx = (p >> 7) & 15, y = (p >> 11) & 15, b = p >> 15;
        float m = (g_m2[p] + g_s2[p]) - g_o2[p];
        float o = (m > 1.0f) ? 1.0f : 0.0f;
        g_m2[p] = m;
        g_o2[p] = o;
        g_a3[((b*18 + y + 1)*18 + xx + 1)*128 + c] = __float2bfloat16(o);
    } else if (i < 966656) {
        int p = i - 835584;                  // (b, 8py, 8px, 128c)
        int c = p & 127, px = (p >> 7) & 7, py = (p >> 10) & 7, b = p >> 13;
        float sum = 0.f;
        #pragma unroll
        for (int dy = 0; dy < 2; dy++)
            #pragma unroll
            for (int dx = 0; dx < 2; dx++) {
                int idx = ((b*16 + 2*py + dy)*16 + 2*px + dx)*128 + c;
                float m = (g_m3[idx] + g_s3[idx]) - g_o3[idx];
                float o = (m > 1.0f) ? 1.0f : 0.0f;
                g_m3[idx] = m;
                g_o3[idx] = o;
                sum += o;
            }
        g_f[b*8192 + c*64 + py*8 + px] = sum * 0.25f;
    } else if (i < 983040) {
        int p = i - 966656;
        float inp = 0.f;
        #pragma unroll 8
        for (int k = 0; k < 32; k++) inp += g_s4[k][p];
        float m = (g_m4[p] + inp) - g_o4[p];
        g_m4[p] = m;
        g_o4[p] = (m > 1.0f) ? 1.0f : 0.0f;
    } else if (i < 999424) {
        int p = i - 983040;
        float inp = ((g_s5[0][p] + g_s5[1][p]) + g_s5[2][p]) + g_s5[3][p];
        float m = (g_m5[p] + inp) - g_o5[p];
        g_m5[p] = m;
        g_o5[p] = (m > 1.0f) ? 1.0f : 0.0f;
    }
}

// ---------------- tensor-core conv tile (R9 geometry, SINGLE sync per stage) ----
// tile: b x 2 y-rows (y0) x 128 oc, K = 3 terms x 9 dydx x CIN.
// 8 warps: wm = wid&1 (y-row), wn = wid>>1 (32-oc group); warp = m16 x n32.
// A slab smem: 4 rows x 18 px x (CIN+8) bf16, loaded once.
// B: k64 x 128 stage (row pad 272B), cp.async double-buffered.
// Pipeline per stage s: wait_group(0) -> ONE __syncthreads (certifies both
// "stage s landed" and "all warps finished compute s-1") -> issue s+1 into
// buf^1 (safe: buf^1 was read at s-1) -> compute s. Barriers halved vs R9.
__device__ __forceinline__ void gemm_conv_tile(
    const __nv_bfloat16* __restrict__ act, const __nv_bfloat16* __restrict__ Wt,
    float* __restrict__ slab, int CIN, int H, int b, int y0, float* smf)
{
    const int PS = CIN + 8;
    __nv_bfloat16* As = (__nv_bfloat16*)smf;
    __nv_bfloat16* Bs = As + 4*18*PS;
    unsigned as_u = (unsigned)__cvta_generic_to_shared(As);
    unsigned bs_u = (unsigned)__cvta_generic_to_shared(Bs);
    const int tid = threadIdx.x, wid = tid >> 5, lane = tid & 31;
    const int wm = wid & 1, wn = wid >> 1;
    const int mr = lane & 15, kh = lane >> 4;

    // prefetch B stage 0 into buf 0
    const __nv_bfloat16* nxt = Wt;
    #pragma unroll
    for (int j = 0; j < 4; j++) {
        int i = tid + j*256;
        unsigned d = bs_u + (i >> 4)*272 + (i & 15)*16;
        asm volatile("cp.async.cg.shared.global [%0], [%1], 16;\n"
                     :: "r"(d), "l"(nxt + i*8) : "memory");
    }
    asm volatile("cp.async.commit_group;\n" ::: "memory");
    nxt += 8192;

    // fill A slab (4 halo rows x 18 px x CIN), px stride padded to PS
    {
        const int cpp = CIN >> 3;             // 16B chunks per pixel
        const int CPR = 18 * cpp;             // chunks per row
        const int TOT = 4 * CPR;
        for (int i = tid; i < TOT; i += 256) {
            int r  = i / CPR; int rr = i - r*CPR;
            int px = rr / cpp; int inner = rr - px*cpp;
            uint4 v = *(const uint4*)(act + (((b*18 + y0 + r)*18 + px)*CIN) + inner*8);
            *(uint4*)(As + (r*18 + px)*PS + inner*8) = v;
        }
    }

    float d0[4], d1[4], d2[4], d3[4];
    #pragma unroll
    for (int nb = 0; nb < 4; nb++) { d0[nb]=0.f; d1[nb]=0.f; d2[nb]=0.f; d3[nb]=0.f; }

    int buf = 0;
    const int nst = 27 * H;
    int s = 0;
    #pragma unroll 1
    for (int t3 = 0; t3 < 3; t3++)
    for (int dy = 0; dy < 3; dy++)
    for (int dx = 0; dx < 3; dx++) {
        unsigned a_base = as_u + (unsigned)((((wm + dy)*18 + mr + dx)*PS + kh*8) * 2);
        #pragma unroll 1
        for (int h = 0; h < H; h++, s++) {
            asm volatile("cp.async.wait_group 0;\n" ::: "memory");
            __syncthreads();
            if (s + 1 < nst) {
                #pragma unroll
                for (int j = 0; j < 4; j++) {
                    int i = tid + j*256;
                    unsigned dd = bs_u + (buf ^ 1)*17408 + (i >> 4)*272 + (i & 15)*16;
                    asm volatile("cp.async.cg.shared.global [%0], [%1], 16;\n"
                                 :: "r"(dd), "l"(nxt + i*8) : "memory");
                }
                asm volatile("cp.async.commit_group;\n" ::: "memory");
                nxt += 8192;
            }
            unsigned bb = bs_u + buf*17408;
            unsigned arow = a_base + h*128;
            #pragma unroll
            for (int k16 = 0; k16 < 4; k16++) {
                unsigned r0, r1, r2, r3;
                asm volatile("ldmatrix.sync.aligned.m8n8.x4.shared.b16 {%0,%1,%2,%3}, [%4];\n"
                             : "=r"(r0), "=r"(r1), "=r"(r2), "=r"(r3)
                             : "r"(arow + k16*32));
                unsigned brow = bb + (unsigned)((k16*16 + mr)*272 + wn*64);
                #pragma unroll
                for (int nb = 0; nb < 4; nb++) {
                    unsigned p0, p1;
                    asm volatile("ldmatrix.sync.aligned.m8n8.x2.trans.shared.b16 {%0,%1}, [%2];\n"
                                 : "=r"(p0), "=r"(p1) : "r"(brow + nb*16));
                    asm volatile("mma.sync.aligned.m16n8k16.row.col.f32.bf16.bf16.f32 "
                                 "{%0,%1,%2,%3}, {%4,%5,%6,%7}, {%8,%9}, {%0,%1,%2,%3};\n"
                                 : "+f"(d0[nb]), "+f"(d1[nb]), "+f"(d2[nb]), "+f"(d3[nb])
                                 : "r"(r0), "r"(r1), "r"(r2), "r"(r3), "r"(p0), "r"(p1));
                }
            }
            buf ^= 1;
        }
    }
    // store accumulators: frag row = x, cols = oc
    int xr = lane >> 2, nc0 = (lane & 3)*2;
    float* obase = slab + (((b*16 + y0 + wm)*16 + xr)*128 + wn*32 + nc0);
    #pragma unroll
    for (int nb = 0; nb < 4; nb++) {
        *(float2*)(obase + nb*8)        = make_float2(d0[nb], d1[nb]);
        *(float2*)(obase + nb*8 + 1024) = make_float2(d2[nb], d3[nb]);
    }
}

// ---------------- conv1 tile (3 in-ch, 32x32), 4 units of 256 ----------------
__device__ __forceinline__ void conv1_tile(
    const float* __restrict__ s, const float* __restrict__ W1,
    float* __restrict__ slab, int tile, float* sm)
{
    int tid = threadIdx.x;
    for (int idx = tid; idx < 1728; idx += 256) sm[idx] = W1[idx];
    __syncthreads();
    #pragma unroll 1
    for (int u4 = 0; u4 < 4; u4++) {
        int u   = (tile*4 + u4)*256 + tid;
        int row = u >> 2;
        int xb  = (u & 3) * 8;
        int b   = row >> 11;
        int oc  = (row >> 5) & 63;
        int y   = row & 31;
        float acc[8];
        #pragma unroll
        for (int i = 0; i < 8; i++) acc[i] = 0.f;
        #pragma unroll
        for (int c = 0; c < 3; c++) {
            #pragma unroll
            for (int dy = 0; dy < 3; dy++) {
                int gy = y + dy - 1;
                if ((unsigned)gy >= 32u) continue;
                const float* srow = s + ((b*3 + c)*32 + gy)*32;
                float iv[10];
                #pragma unroll
                for (int t = 0; t < 10; t++) {
                    int gx = xb + t - 1;
                    iv[t] = ((unsigned)gx < 32u) ? srow[gx] : 0.f;
                }
                float w[3];
                #pragma unroll
                for (int dx = 0; dx < 3; dx++) w[dx] = sm[oc*27 + c*9 + dy*3 + dx];
                #pragma unroll
                for (int i = 0; i < 8; i++)
                    #pragma unroll
                    for (int dx = 0; dx < 3; dx++)
                        acc[i] += iv[i + dx] * w[dx];
            }
        }
        int base = ((b*64 + oc)*32 + y)*32 + xb;
        #pragma unroll
        for (int i = 0; i < 8; i++) slab[base + i] = acc[i];
    }
}

// ---------------- FC tile: out[b,j] = A[b,k0:k0+256] . W[j,k0:k0+256] ----------------
__device__ __forceinline__ void fc_tile(
    const float* __restrict__ A, const float* __restrict__ W,
    float* __restrict__ out, int K, int j0, int k0, float* sm)
{
    float* fs = sm;          // [16][64]
    float* ws = sm + 1024;   // [64][65]
    int tid = threadIdx.x;
    int tj  = tid & 31;
    int tb  = tid >> 5;
    float acc[2][2] = {{0.f,0.f},{0.f,0.f}};
    #pragma unroll 1
    for (int kc = k0; kc < k0 + 256; kc += 64) {
        __syncthreads();
        for (int idx = tid; idx < 1024; idx += 256) {
            int bb = idx >> 6, kk = idx & 63;
            fs[idx] = A[bb*K + kc + kk];
        }
        for (int idx = tid; idx < 4096; idx += 256) {
            int jl = idx >> 6, kk = idx & 63;
            ws[jl*65 + kk] = W[(j0 + jl)*K + kc + kk];
        }
        __syncthreads();
        #pragma unroll 4
        for (int kk = 0; kk < 64; kk++) {
            float w0 = ws[(tj*2    )*65 + kk];
            float w1 = ws[(tj*2 + 1)*65 + kk];
            float f0 = fs[ tb      *64 + kk];
            float f1 = fs[(tb + 8) *64 + kk];
            acc[0][0] += w0*f0;  acc[0][1] += w0*f1;
            acc[1][0] += w1*f0;  acc[1][1] += w1*f1;
        }
    }
    #pragma unroll
    for (int q = 0; q < 2; q++)
        #pragma unroll
        for (int r = 0; r < 2; r++)
            out[(tb + r*8)*1024 + (j0 + tj*2 + q)] = acc[q][r];
}

// ---------------- fc3: mo += o5 @ L3^T ----------------
__device__ __forceinline__ void fc3_part(
    const float* __restrict__ o5, const float* __restrict__ L3, float* __restrict__ mo)
{
    int t = threadIdx.x;
    if (t >= 160) return;
    int b = t / 10, j = t - b*10;
    const float* a = o5 + b*1024;
    const float* w = L3 + j*1024;
    float acc = 0.f;
    #pragma unroll 4
    for (int k = 0; k < 1024; k++) acc += a[k]*w[k];
    mo[t] += acc;
}

// ---------------- fat per-step kernel: work queue over 961 tiles ----------------
__global__ void __launch_bounds__(256, 4) conv_step(
    const float* __restrict__ W1, const float* __restrict__ L1,
    const float* __restrict__ L2, const float* __restrict__ L3)
{
    extern __shared__ float smf[];
    __shared__ int s_tile;
    for (;;) {
        __syncthreads();
        if (threadIdx.x == 0) s_tile = atomicAdd(&g_tick, 1);
        __syncthreads();
        int t = s_tile;
        if (t >= NT) return;
        if (t < 128) {                       // conv3 TC: 16b x 8 y-pairs
            int b = t >> 3, y0 = (t & 7)*2;
            gemm_conv_tile(g_a3, g_w3t, g_s3, 128, 2, b, y0, smf);
        } else if (t < 256) {                // conv2 TC
            int i = t - 128;
            int b = i >> 3, y0 = (i & 7)*2;
            gemm_conv_tile(g_a2, g_w2t, g_s2, 64, 1, b, y0, smf);
        } else if (t < 768) {                // fc1: 16jg x 32ks
            int i = t - 256;
            int jg = i & 15, ks = i >> 4;
            fc_tile(g_f, L1, &g_s4[ks][0], 8192, jg*64, ks*256, smf);
        } else if (t < 896) {                // conv1: 128 tiles x 4 units
            conv1_tile(g_s, W1, g_c1s, t - 768, smf);
        } else if (t < 960) {                // fc2: 16jg x 4ks
            int i = t - 896;
            int jg = i & 15, ks = i >> 4;
            fc_tile(g_o4, L2, &g_s5[ks][0], 1024, jg*64, ks*256, smf);
        } else {                             // fc3
            fc3_part(g_o5, L3, g_mo);
        }
    }
}

__global__ void write_out(float* __restrict__ out) {
    int t = threadIdx.x;
    if (t < 160) out[t] = g_mo[t];
}

extern "C" void kernel_launch(void* const* d_in, const int* in_sizes, int n_in,
                              void* d_out, int out_size)
{
    const float* x  = (const float*)d_in[0];
    const float* W1 = (const float*)d_in[1];
    const float* W2 = (const float*)d_in[2];
    const float* W3 = (const float*)d_in[3];
    const float* L1 = (const float*)d_in[4];
    const float* L2 = (const float*)d_in[5];
    const float* L3 = (const float*)d_in[6];

    cudaFuncSetAttribute(conv_step, cudaFuncAttributeMaxDynamicSharedMemorySize, SMEM_BYTES);

    zero_state<<<512, 256>>>();
    prep_weights<<<864, 256>>>(W2, W3);
    for (int t = 0; t < T_STEPS; t++) {
        spike_step<<<3904, 256>>>(x);
        conv_step<<<GRID_CONV, 256, SMEM_BYTES>>>(W1, L1, L2, L3);
    }
    write_out<<<1, 192>>>((float*)d_out);
}